// round 4
// baseline (speedup 1.0000x reference)
#include <cuda_runtime.h>
#include <math.h>

#define NBATCH 8
#define DPIX   147456       // 384*384
#define KB     256          // fine-grid bins
#define BINS   50
#define B_ROW  258          // odd-parity array row stride (even -> 8B align w/ +1)
#define B_TOT  (NBATCH*KB*B_ROW + 4)

// Scratch. __device__ globals are zero-initialized at module load; the
// histogram arrays are returned to all-zero by k_stageC on every call.
__device__ __align__(16) float g_A[NBATCH * KB * KB];   // even-j0 histogram (2 MB)
__device__ __align__(16) float g_Braw[B_TOT];           // odd-j0 histogram (+1 float offset)
__device__ __align__(16) float g_G [BINS * KB];         // G[b][i]
__device__ __align__(16) float g_GT[KB * BINS];         // GT[i][b]
__device__ __align__(16) float g_P [8 * NBATCH * BINS * KB]; // P partials [ic][n][b][j] (3.2MB)
__device__ __align__(16) float g_hgram[NBATCH * BINS * BINS];

// ---------------- Kernel 1: histogram (bilinear, vector REDs) + G table -------
__device__ __forceinline__ void red2(float* p, float a, float b) {
    asm volatile("red.global.add.v2.f32 [%0], {%1, %2};"
                 :: "l"(p), "f"(a), "f"(b) : "memory");
}

__global__ void k_hist(const float* __restrict__ im1, const float* __restrict__ im2) {
    int gid = blockIdx.x * blockDim.x + threadIdx.x;   // one float4 chunk (4 pixels)

    // fold G-table computation into the first BINS*KB threads
    if (gid < BINS * KB) {
        int b = gid / KB, i = gid % KB;
        float x = (i + 0.5f) * (1.0f / KB);
        float c = (b + 0.5f) * 0.02f;
        float d = 10.0f * (x - c);
        float s1 = 1.0f / (1.0f + expf(-(d + 0.1f)));
        float s2 = 1.0f / (1.0f + expf(-(d - 0.1f)));
        float v = s1 - s2;
        g_G [b * KB   + i] = v;
        g_GT[i * BINS + b] = v;
    }

    const int nchunk = (NBATCH * DPIX) / 4;
    if (gid >= nchunk) return;
    int n = gid / (DPIX / 4);                  // 36864 chunks per batch, no straddle
    float4 xv = ((const float4*)im1)[gid];
    float4 yv = ((const float4*)im2)[gid];
    size_t baseA = (size_t)n * KB * KB;
    size_t baseB = (size_t)n * KB * B_ROW;

    float xs[4] = {xv.x, xv.y, xv.z, xv.w};
    float ys[4] = {yv.x, yv.y, yv.z, yv.w};
#pragma unroll
    for (int q = 0; q < 4; q++) {
        float u = xs[q] * (float)KB - 0.5f;
        float fi = fminf((float)(KB - 2), fmaxf(0.0f, floorf(u)));
        int   i0 = (int)fi;
        float wx = u - fi;
        float v  = ys[q] * (float)KB - 0.5f;
        float fj = fminf((float)(KB - 2), fmaxf(0.0f, floorf(v)));
        int   j0 = (int)fj;
        float wy = v - fj;
        float ax = 1.0f - wx, ay = 1.0f - wy;

        bool odd = (j0 & 1);
        float* arr = odd ? (g_Braw + 1 + baseB) : (g_A + baseA);
        int    rs  = odd ? B_ROW : KB;
        float* p   = arr + (size_t)i0 * rs + j0;     // 8B-aligned by parity
        red2(p,      ax * ay, ax * wy);
        red2(p + rs, wx * ay, wx * wy);
    }
}

// ---------------- Kernel 2: P[ic][n][b][j] = sum_i G[b][i]*H[n][i][j]; re-zero H
// grid = 8(n) * 8(ic: 32 i-rows) * 2(jt: 128 j) = 128 blocks, 128 threads
__global__ void __launch_bounds__(128) k_stageC() {
    int blk = blockIdx.x;
    int n  = blk >> 4;
    int ic = (blk >> 1) & 7;
    int jt = blk & 1;
    int j  = jt * 128 + threadIdx.x;
    int i_beg = ic * 32;

    __shared__ float Gs[32][BINS + 2];
    for (int t = threadIdx.x; t < 32 * BINS; t += 128) {
        int ii = t / BINS, k = t % BINS;
        Gs[ii][k] = g_GT[(i_beg + ii) * BINS + k];
    }
    __syncthreads();

    float acc[BINS];
#pragma unroll
    for (int k = 0; k < BINS; k++) acc[k] = 0.0f;

    float* A = g_A    +     (size_t)n * KB * KB    + (size_t)i_beg * KB    + j;
    float* B = g_Braw + 1 + (size_t)n * KB * B_ROW + (size_t)i_beg * B_ROW + j;

#pragma unroll 4
    for (int ii = 0; ii < 32; ii++) {
        float h = A[(size_t)ii * KB] + B[(size_t)ii * B_ROW];
        A[(size_t)ii * KB]    = 0.0f;    // restore all-zero state for next call
        B[(size_t)ii * B_ROW] = 0.0f;
#pragma unroll
        for (int k = 0; k < BINS; k++) acc[k] += h * Gs[ii][k];
    }

    size_t pb = (((size_t)ic * NBATCH + n) * BINS) * KB + j;
#pragma unroll
    for (int k = 0; k < BINS; k++) g_P[pb + (size_t)k * KB] = acc[k];
}

// ---------------- Kernel 3: hgram[nb][c] = sum_j (sum_ic P)[nb][j] * G[c][j] --
// grid = 400 (nb = n*50+b), 128 threads
__global__ void __launch_bounds__(128) k_stageD() {
    int nb = blockIdx.x;
    __shared__ float Ps[KB];
    const int PSTRIDE = NBATCH * BINS * KB;
    const float* P = g_P + (size_t)nb * KB;
#pragma unroll
    for (int t = 0; t < 2; t++) {
        int jj = threadIdx.x + t * 128;
        float s = 0.0f;
#pragma unroll
        for (int ic = 0; ic < 8; ic++) s += P[jj + ic * PSTRIDE];
        Ps[jj] = s;
    }
    __syncthreads();

    int c = threadIdx.x;
    if (c < BINS) {
        const float* Gc = g_G + (size_t)c * KB;
        float a0 = 0.f, a1 = 0.f, a2 = 0.f, a3 = 0.f;
#pragma unroll
        for (int q = 0; q < KB; q += 4) {
            a0 += Ps[q]     * __ldg(Gc + q);
            a1 += Ps[q + 1] * __ldg(Gc + q + 1);
            a2 += Ps[q + 2] * __ldg(Gc + q + 2);
            a3 += Ps[q + 3] * __ldg(Gc + q + 3);
        }
        g_hgram[(size_t)nb * BINS + c] = (a0 + a1) + (a2 + a3);
    }
}

// ---------------- Kernel 4: normalize, marginals, MI --------------------------
__global__ void __launch_bounds__(1024) k_stageE(float* __restrict__ out) {
    __shared__ float red[1024];
    __shared__ float mx[NBATCH * BINS], my[NBATCH * BINS];
    __shared__ float sS;
    int tid = threadIdx.x;
    const int TOT = NBATCH * BINS * BINS;    // 20000

    // total sum (vectorized: 5000 float4)
    float s = 0.0f;
    const float4* H4 = (const float4*)g_hgram;
    for (int t = tid; t < TOT / 4; t += 1024) {
        float4 v = H4[t];
        s += (v.x + v.y) + (v.z + v.w);
    }
    red[tid] = s; __syncthreads();
    for (int o = 512; o; o >>= 1) { if (tid < o) red[tid] += red[tid + o]; __syncthreads(); }
    if (tid == 0) sS = red[0];

    // marginals
    if (tid < NBATCH * BINS) {
        int n = tid / BINS, b = tid % BINS;
        const float* Hn = g_hgram + (size_t)n * BINS * BINS;
        float m1 = 0.0f, m2 = 0.0f;
        for (int c = 0; c < BINS; c++) { m1 += Hn[b * BINS + c]; m2 += Hn[c * BINS + b]; }
        mx[tid] = m1; my[tid] = m2;
    }
    __syncthreads();

    // MI: p*(log(p+eps) - log(q+eps)) == p*log((p+eps)/(q+eps)); fast log
    float inv = 1.0f / sS;
    float mi = 0.0f;
    for (int t = tid; t < TOT; t += 1024) {
        int n = t / (BINS * BINS);
        int rem = t - n * (BINS * BINS);
        int b = rem / BINS, c = rem % BINS;
        float p = g_hgram[t] * inv;
        float q = (mx[n * BINS + b] * inv) * (my[n * BINS + c] * inv);
        mi += p * __logf(__fdividef(p + 1e-8f, q + 1e-8f));
    }
    red[tid] = mi; __syncthreads();
    for (int o = 512; o; o >>= 1) { if (tid < o) red[tid] += red[tid + o]; __syncthreads(); }
    if (tid == 0) out[0] = red[0];
}

// ---------------- Launch -------------------------------------------------------
extern "C" void kernel_launch(void* const* d_in, const int* in_sizes, int n_in,
                              void* d_out, int out_size) {
    const float* im1 = (const float*)d_in[0];
    const float* im2 = (const float*)d_in[1];
    k_hist  <<<(NBATCH * DPIX / 4 + 255) / 256, 256>>>(im1, im2);
    k_stageC<<<128, 128>>>();
    k_stageD<<<400, 128>>>();
    k_stageE<<<1, 1024>>>((float*)d_out);
}

// round 5
// speedup vs baseline: 1.6568x; 1.6568x over previous
#include <cuda_runtime.h>
#include <math.h>

#define NBATCH 8
#define DPIX   147456     // 384*384
#define KBINS  256
#define BINS   50
#define B_ROW  258        // odd-parity array row stride (even, keeps 8B align)
#define B_TOT  (NBATCH*KBINS*B_ROW + 4)   // divisible by 4

// Scratch (device globals; no dynamic allocation allowed)
__device__ __align__(16) float g_A[NBATCH * KBINS * KBINS];  // even-j0 histogram (2 MB)
__device__ __align__(16) float g_Braw[B_TOT];                // odd-j0 histogram (+1 float offset)
__device__ __align__(16) float g_G [BINS * KBINS];           // G[b][i]
__device__ __align__(16) float g_GT[KBINS * BINS];           // GT[i][b]
__device__ __align__(16) float g_P [2 * NBATCH * BINS * KBINS];  // P halves [is][n][b][j]
__device__ __align__(16) float g_hgram[NBATCH * BINS * BINS];
__device__ float g_mx[NBATCH * BINS];   // row marginals (written exactly once per call)
__device__ float g_my[NBATCH * BINS];   // col marginals (atomic-accumulated)
__device__ float g_S;                   // grand total    (atomic-accumulated)

// ---------------- Kernel 1: zero scratch + precompute soft-bin kernel G -------
__global__ void k_init(float* __restrict__ out) {
    int gid = blockIdx.x * blockDim.x + threadIdx.x;
    int stride = gridDim.x * blockDim.x;
    if (gid == 0) { g_S = 0.0f; out[0] = 0.0f; }
    if (gid < NBATCH * BINS) g_my[gid] = 0.0f;

    float4 z = make_float4(0.f, 0.f, 0.f, 0.f);
    float4* A4 = (float4*)g_A;
    int totA = (NBATCH * KBINS * KBINS) / 4;
    for (int t = gid; t < totA; t += stride) A4[t] = z;
    float4* B4 = (float4*)g_Braw;
    int totB = B_TOT / 4;
    for (int t = gid; t < totB; t += stride) B4[t] = z;

    for (int t = gid; t < BINS * KBINS; t += stride) {
        int b = t / KBINS, i = t % KBINS;
        double x = (i + 0.5) / (double)KBINS;
        double c = (b + 0.5) * 0.02;
        double d = 10.0 * (x - c);
        double s1 = 1.0 / (1.0 + exp(-(d + 0.1)));
        double s2 = 1.0 / (1.0 + exp(-(d - 0.1)));
        float v = (float)(s1 - s2);
        g_G [b * KBINS + i] = v;
        g_GT[i * BINS  + b] = v;
    }
}

// ---------------- Kernel 2: bilinear 2D histogram with vector REDs ------------
__device__ __forceinline__ void red2(float* p, float a, float b) {
    asm volatile("red.global.add.v2.f32 [%0], {%1, %2};"
                 :: "l"(p), "f"(a), "f"(b) : "memory");
}

__global__ void k_hist(const float* __restrict__ im1, const float* __restrict__ im2) {
    int gid = blockIdx.x * blockDim.x + threadIdx.x;   // one float4 chunk (4 pixels)
    const int nchunk = (NBATCH * DPIX) / 4;
    if (gid >= nchunk) return;
    int n = gid / (DPIX / 4);   // 36864 chunks per batch, no straddle
    float4 xv = ((const float4*)im1)[gid];
    float4 yv = ((const float4*)im2)[gid];
    size_t baseA = (size_t)n * KBINS * KBINS;
    size_t baseB = (size_t)n * KBINS * B_ROW;

    float xs[4] = {xv.x, xv.y, xv.z, xv.w};
    float ys[4] = {yv.x, yv.y, yv.z, yv.w};
#pragma unroll
    for (int q = 0; q < 4; q++) {
        float u = xs[q] * 256.0f - 0.5f;
        float fi = fminf(254.0f, fmaxf(0.0f, floorf(u)));
        int   i0 = (int)fi;
        float wx = u - fi;
        float v  = ys[q] * 256.0f - 0.5f;
        float fj = fminf(254.0f, fmaxf(0.0f, floorf(v)));
        int   j0 = (int)fj;
        float wy = v - fj;
        float ax = 1.0f - wx, ay = 1.0f - wy;

        bool odd = (j0 & 1);
        float* arr = odd ? (g_Braw + 1 + baseB) : (g_A + baseA);
        int    rs  = odd ? B_ROW : KBINS;
        float* p   = arr + (size_t)i0 * rs + j0;   // 8B-aligned by parity construction
        red2(p,      ax * ay, ax * wy);
        red2(p + rs, wx * ay, wx * wy);
    }
}

// ---------------- Kernel 3: P[is][n][b][j] = sum_{i in half} G[b][i]*H[n][i][j]
// grid = 160 blocks, 128 threads
__global__ void k_stageC() {
    int blk = blockIdx.x;
    int n  = blk / 20;
    int r  = blk % 20;
    int jt = r / 10;
    int r2 = r % 10;
    int bg = r2 / 2, is = r2 % 2;
    int j  = jt * 128 + threadIdx.x;
    int b0 = bg * 10;
    int i_beg = is * 128;

    __shared__ float Gs[64][12];   // 48B rows -> float4-aligned
    float acc[10];
#pragma unroll
    for (int k = 0; k < 10; k++) acc[k] = 0.0f;

    const float* A = g_A    +      (size_t)n * KBINS * KBINS + j;
    const float* B = g_Braw + 1 +  (size_t)n * KBINS * B_ROW + j;

    for (int it = i_beg; it < i_beg + 128; it += 64) {
        __syncthreads();
        for (int t = threadIdx.x; t < 640; t += 128) {
            int ii = t / 10, k = t % 10;
            Gs[ii][k] = g_GT[(it + ii) * BINS + b0 + k];
        }
        __syncthreads();
#pragma unroll 8
        for (int ii = 0; ii < 64; ii++) {
            int i = it + ii;
            float h = A[(size_t)i * KBINS] + B[(size_t)i * B_ROW];
            float4 ga = *(const float4*)&Gs[ii][0];
            float4 gb = *(const float4*)&Gs[ii][4];
            float2 gc = *(const float2*)&Gs[ii][8];
            acc[0] += h * ga.x; acc[1] += h * ga.y; acc[2] += h * ga.z; acc[3] += h * ga.w;
            acc[4] += h * gb.x; acc[5] += h * gb.y; acc[6] += h * gb.z; acc[7] += h * gb.w;
            acc[8] += h * gc.x; acc[9] += h * gc.y;
        }
    }
    size_t pb = (((size_t)is * NBATCH + n) * BINS + b0) * KBINS + j;
#pragma unroll
    for (int k = 0; k < 10; k++) g_P[pb + (size_t)k * KBINS] = acc[k];
}

// ---------------- Kernel 4: hgram row + marginals + total ---------------------
// grid = 400 (nb = n*50+b), 256 threads
__global__ void k_stageD() {
    int nb = blockIdx.x;
    int n  = nb / BINS;
    __shared__ float Ps[KBINS];
    __shared__ float rows[BINS];
    const float* P0 = g_P + (size_t)nb * KBINS;
    const float* P1 = g_P + (size_t)(NBATCH * BINS + nb) * KBINS;
    for (int t = threadIdx.x; t < KBINS; t += 256) Ps[t] = P0[t] + P1[t];
    __syncthreads();
    int w = threadIdx.x >> 5, lane = threadIdx.x & 31;
    for (int c = w; c < BINS; c += 8) {
        const float* Gc = g_G + (size_t)c * KBINS;
        float s0 = 0.0f, s1 = 0.0f;
#pragma unroll
        for (int q = 0; q < KBINS / 64; q++) {
            int jj = q * 64 + lane;
            s0 += Ps[jj]      * Gc[jj];
            s1 += Ps[jj + 32] * Gc[jj + 32];
        }
        float s = s0 + s1;
#pragma unroll
        for (int o = 16; o; o >>= 1) s += __shfl_xor_sync(0xffffffffu, s, o);
        if (lane == 0) {
            g_hgram[(size_t)nb * BINS + c] = s;
            rows[c] = s;
            atomicAdd(&g_my[n * BINS + c], s);
        }
    }
    __syncthreads();
    if (threadIdx.x == 0) {
        float r = 0.0f;
#pragma unroll
        for (int c = 0; c < BINS; c++) r += rows[c];
        g_mx[nb] = r;
        atomicAdd(&g_S, r);
    }
}

// ---------------- Kernel 5: MI terms, distributed ------------------------------
// grid = 400 (nb), 64 threads
__global__ void __launch_bounds__(64) k_stageE(float* __restrict__ out) {
    int nb = blockIdx.x;
    int n  = nb / BINS;
    int c  = threadIdx.x;
    float inv = 1.0f / g_S;
    float mi = 0.0f;
    if (c < BINS) {
        float p = g_hgram[(size_t)nb * BINS + c] * inv;
        float q = (g_mx[nb] * inv) * (g_my[n * BINS + c] * inv);
        mi = p * __logf(__fdividef(p + 1e-8f, q + 1e-8f));
    }
#pragma unroll
    for (int o = 16; o; o >>= 1) mi += __shfl_xor_sync(0xffffffffu, mi, o);
    __shared__ float wsum[2];
    if ((threadIdx.x & 31) == 0) wsum[threadIdx.x >> 5] = mi;
    __syncthreads();
    if (threadIdx.x == 0) atomicAdd(out, wsum[0] + wsum[1]);
}

// ---------------- Launch -------------------------------------------------------
extern "C" void kernel_launch(void* const* d_in, const int* in_sizes, int n_in,
                              void* d_out, int out_size) {
    const float* im1 = (const float*)d_in[0];
    const float* im2 = (const float*)d_in[1];
    k_init  <<<512, 256>>>((float*)d_out);
    k_hist  <<<(NBATCH * DPIX / 4 + 255) / 256, 256>>>(im1, im2);
    k_stageC<<<160, 128>>>();
    k_stageD<<<400, 256>>>();
    k_stageE<<<400, 64>>>((float*)d_out);
}